// round 13
// baseline (speedup 1.0000x reference)
#include <cuda_runtime.h>
#include <cuda_bf16.h>
#include <cstdint>
#include <math.h>

#define NQ 256
#define ND 256
#define NI 2048
#define KTOT 512          // concat K: [yg | yg^2]
#define SE_INV_TEMP 5.0f
#define BN_EPS 1e-5f

// GEMM tile config
#define TM 64             // M tile (gallery i)
#define TN 64             // N tile (2 cols per query: num, den) -> 32 q per block
#define KC 128            // K per chunk (128 bf16 = 256 bytes per row)
#define NCHUNK (KTOT / KC)      // 4 per pass
#define NPASS 3                 // Ah*Bh, Ah*Bl, Al*Bh
#define NCHTOT (NPASS * NCHUNK) // 12
#define LDAB 136          // smem row stride in bf16 (128 + 8 pad = 272 bytes)
#define A_STAGE_B (TM * LDAB * 2)            // 17408
#define B_STAGE_B (TN * LDAB * 2)            // 17408
#define STAGE_B (A_STAGE_B + B_STAGE_B)      // 34816
#define SMEM_BYTES (2 * STAGE_B)             // 69632 -> 2 CTAs/SM guaranteed
#define LDS_SC 68         // float stride for score transpose (64 + 4)

// ---- device scratch (no allocs allowed) ----
__device__ __nv_bfloat16 g_Ahi[NI * KTOT];     // [i][yg(256) | yg^2(256)] hi
__device__ __nv_bfloat16 g_Alo[NI * KTOT];     // lo residual
__device__ __nv_bfloat16 g_Bhi[2 * NQ * KTOT]; // row 2q=[A1|0], 2q+1=[A3|A2] hi
__device__ __nv_bfloat16 g_Blo[2 * NQ * KTOT]; // lo residual
__device__ float g_c1[NQ];
__device__ float g_B;

__device__ __forceinline__ uint32_t smem_to_u32(const void* p) {
    uint32_t a;
    asm("{ .reg .u64 t; cvta.to.shared.u64 t, %1; cvt.u32.u64 %0, t; }"
        : "=r"(a) : "l"(p));
    return a;
}
#define CP_ASYNC16(dst_u32, src_ptr) \
    asm volatile("cp.async.cg.shared.global [%0], [%1], 16;" \
                 :: "r"(dst_u32), "l"(src_ptr) : "memory")
#define CP_COMMIT() asm volatile("cp.async.commit_group;" ::: "memory")
#define CP_WAIT1() asm volatile("cp.async.wait_group 1;" ::: "memory")
#define CP_WAIT0() asm volatile("cp.async.wait_group 0;" ::: "memory")

__device__ __forceinline__ float warpSum(float v) {
#pragma unroll
    for (int o = 16; o > 0; o >>= 1) v += __shfl_xor_sync(0xffffffffu, v, o);
    return v;
}
__device__ __forceinline__ uint32_t pk2(float a, float b) {
    __nv_bfloat162 h = __floats2bfloat162_rn(a, b);
    return *reinterpret_cast<uint32_t*>(&h);
}
__device__ __forceinline__ void st8bf(__nv_bfloat16* p, const float* v) {
    uint4 u;
    u.x = pk2(v[0], v[1]); u.y = pk2(v[2], v[3]);
    u.z = pk2(v[4], v[5]); u.w = pk2(v[6], v[7]);
    *reinterpret_cast<uint4*>(p) = u;
}
// store hi/lo split of 8 floats
__device__ __forceinline__ void st8split(__nv_bfloat16* phi, __nv_bfloat16* plo,
                                         const float* v) {
    float hi[8], lo[8];
#pragma unroll
    for (int j = 0; j < 8; ++j) {
        __nv_bfloat16 h = __float2bfloat16(v[j]);
        hi[j] = __bfloat162float(h);
        lo[j] = v[j] - hi[j];
    }
    st8bf(phi, hi);
    st8bf(plo, lo);
}

// ---- fused prep: blocks [0,256) gallery rows, [256,288) query rows ----
__global__ __launch_bounds__(256) void prep(
    const float* __restrict__ qf, const float* __restrict__ qif,
    const float* __restrict__ gal,
    const float* __restrict__ gamma, const float* __restrict__ beta,
    const float* __restrict__ mean, const float* __restrict__ var) {
    int w = threadIdx.x >> 5, lane = threadIdx.x & 31;
    int d0 = lane * 8;

    if (blockIdx.x < 256) {
        int i = blockIdx.x * 8 + w;
        float v[8];
        *(float4*)&v[0] = *(const float4*)(gal + i * ND + d0);
        *(float4*)&v[4] = *(const float4*)(gal + i * ND + d0 + 4);
        float ss = 0.f;
#pragma unroll
        for (int j = 0; j < 8; ++j) ss += v[j] * v[j];
        ss = warpSum(ss);
        float r = 1.f / fmaxf(sqrtf(ss), 1e-12f);
        float yg[8], yg2[8];
#pragma unroll
        for (int j = 0; j < 8; ++j) { yg[j] = v[j] * r; yg2[j] = yg[j] * yg[j]; }
        st8split(g_Ahi + i * KTOT + d0, g_Alo + i * KTOT + d0, yg);
        st8split(g_Ahi + i * KTOT + ND + d0, g_Alo + i * KTOT + ND + d0, yg2);
    } else {
        int q = (blockIdx.x - 256) * 8 + w;
        float gm[8], bt[8], mn[8], vr[8], x[8], y[8];
        *(float4*)&gm[0] = *(const float4*)(gamma + d0);
        *(float4*)&gm[4] = *(const float4*)(gamma + d0 + 4);
        *(float4*)&bt[0] = *(const float4*)(beta + d0);
        *(float4*)&bt[4] = *(const float4*)(beta + d0 + 4);
        *(float4*)&mn[0] = *(const float4*)(mean + d0);
        *(float4*)&mn[4] = *(const float4*)(mean + d0 + 4);
        *(float4*)&vr[0] = *(const float4*)(var + d0);
        *(float4*)&vr[4] = *(const float4*)(var + d0 + 4);
        *(float4*)&x[0] = *(const float4*)(qf + q * ND + d0);
        *(float4*)&x[4] = *(const float4*)(qf + q * ND + d0 + 4);
        *(float4*)&y[0] = *(const float4*)(qif + q * ND + d0);
        *(float4*)&y[4] = *(const float4*)(qif + q * ND + d0 + 4);

        float s[8], bb[8];
        float nx = 0.f, ny = 0.f;
#pragma unroll
        for (int j = 0; j < 8; ++j) {
            s[j] = gm[j] * rsqrtf(vr[j] + BN_EPS);
            bb[j] = bt[j] - mn[j] * s[j];
            nx += x[j] * x[j];
            ny += y[j] * y[j];
        }
        nx = warpSum(nx); ny = warpSum(ny);
        float rx = 1.f / fmaxf(sqrtf(nx), 1e-12f);
        float ry = 1.f / fmaxf(sqrtf(ny), 1e-12f);

        float ww[8], u[8];
        float nu = 0.f;
#pragma unroll
        for (int j = 0; j < 8; ++j) {
            float xh = x[j] * rx;
            float gate = 1.f / (1.f + __expf(-xh * SE_INV_TEMP));
            ww[j] = gate * s[j];
            u[j] = y[j] * ry * ww[j] + bb[j];
            nu += u[j] * u[j];
        }
        nu = warpSum(nu);
        float ru = 1.f / fmaxf(sqrtf(nu), 1e-12f);

        float a1[8], a2[8], a3[8], zz[8];
        float c1 = 0.f, Bacc = 0.f;
#pragma unroll
        for (int j = 0; j < 8; ++j) {
            float uh = u[j] * ru;
            a1[j] = uh * ww[j];
            a2[j] = ww[j] * ww[j];
            a3[j] = 2.f * ww[j] * bb[j];
            zz[j] = 0.f;
            c1 += uh * bb[j];
            Bacc += bb[j] * bb[j];
        }
        int r0 = (2 * q) * KTOT, r1 = (2 * q + 1) * KTOT;
        st8split(g_Bhi + r0 + d0, g_Blo + r0 + d0, a1);
        st8bf(g_Bhi + r0 + ND + d0, zz);
        st8bf(g_Blo + r0 + ND + d0, zz);
        st8split(g_Bhi + r1 + d0, g_Blo + r1 + d0, a3);
        st8split(g_Bhi + r1 + ND + d0, g_Blo + r1 + ND + d0, a2);

        c1 = warpSum(c1);
        if (lane == 0) g_c1[q] = c1;
        if (q == 0) {
            Bacc = warpSum(Bacc);
            if (lane == 0) g_B = Bacc;
        }
    }
}

// ================= bf16 mma.sync GEMM (split-bf16 x3) + fused epilogue ======
// D = Ah*Bh + Ah*Bl + Al*Bh ; out[q,i] = sigmoid((D[i,2q]+c1)*rsqrt(D[i,2q+1]+B))
__global__ __launch_bounds__(256, 2) void score_mma(float* __restrict__ out) {
    extern __shared__ char smem[];
    const uint32_t smem_u = smem_to_u32(smem);
    const int tid = threadIdx.x;
    const int wid = tid >> 5, lane = tid & 31;
    const int wm = wid & 1;         // 0..1 -> 32-row band
    const int wn = wid >> 1;        // 0..3 -> 16-col band
    const int iBase = blockIdx.x * TM;
    const int nBase = blockIdx.y * TN;
    const int qBase = nBase >> 1;   // 32 q per block

    float c[2][2][4];
#pragma unroll
    for (int a = 0; a < 2; ++a)
#pragma unroll
        for (int b = 0; b < 2; ++b)
#pragma unroll
            for (int e = 0; e < 4; ++e) c[a][b][e] = 0.f;

    // per-thread ldmatrix base offsets (byte offsets within a stage)
    const int lmRow = lane & 15;
    const int lmColB = ((lane >> 4) & 1) * 16;
    uint32_t aOffs[2];
#pragma unroll
    for (int mt = 0; mt < 2; ++mt)
        aOffs[mt] = (uint32_t)((wm * 32 + mt * 16 + lmRow) * (LDAB * 2) + lmColB);
    const uint32_t bOff =
        (uint32_t)(A_STAGE_B + (wn * 16 + lmRow) * (LDAB * 2) + lmColB);

    // cp.async staging: A 64 rows x 16 x 16B = 1024 chunks (4/thread),
    //                   B 64 rows x 16 x 16B = 1024 chunks (4/thread)
    auto ISSUE = [&](int u, int buf) {
        const int p = u >> 2;        // pass: 0=Ah*Bh 1=Ah*Bl 2=Al*Bh
        const int t = u & 3;         // k chunk within pass
        const __nv_bfloat16* As = (p == 2) ? g_Alo : g_Ahi;
        const __nv_bfloat16* Bs = (p == 1) ? g_Blo : g_Bhi;
        uint32_t sA = smem_u + buf * STAGE_B;
        uint32_t sB = sA + A_STAGE_B;
#pragma unroll
        for (int j = 0; j < 4; ++j) {
            int cidx = tid + j * 256;            // [0, 1024)
            int row = cidx >> 4, c16 = cidx & 15;
            CP_ASYNC16(sA + row * (LDAB * 2) + c16 * 16,
                       As + (iBase + row) * KTOT + t * KC + c16 * 8);
        }
#pragma unroll
        for (int j = 0; j < 4; ++j) {
            int cidx = tid + j * 256;            // [0, 1024)
            int row = cidx >> 4, c16 = cidx & 15;
            CP_ASYNC16(sB + row * (LDAB * 2) + c16 * 16,
                       Bs + (nBase + row) * KTOT + t * KC + c16 * 8);
        }
        CP_COMMIT();
    };

    ISSUE(0, 0);

    for (int u = 0; u < NCHTOT; ++u) {
        __syncthreads();   // all warps done computing chunk u-1 -> stage (u+1)&1 reusable
        if (u + 1 < NCHTOT) {
            ISSUE(u + 1, (u + 1) & 1);
            CP_WAIT1();    // group u complete (u+1 may still fly)
        } else {
            CP_WAIT0();
        }
        __syncthreads();   // chunk u data visible to all warps

        const uint32_t stage = smem_u + (u & 1) * STAGE_B;
#pragma unroll
        for (int kk = 0; kk < KC / 16; ++kk) {
            uint32_t a0[2], a1[2], a2[2], a3[2];
#pragma unroll
            for (int mt = 0; mt < 2; ++mt) {
                uint32_t addr = stage + aOffs[mt] + kk * 32;
                asm volatile(
                    "ldmatrix.sync.aligned.m8n8.x4.shared.b16 {%0,%1,%2,%3}, [%4];"
                    : "=r"(a0[mt]), "=r"(a1[mt]), "=r"(a2[mt]), "=r"(a3[mt])
                    : "r"(addr));
            }
            uint32_t b0[2], b1[2];
            {
                uint32_t addr = stage + bOff + kk * 32;
                asm volatile(
                    "ldmatrix.sync.aligned.m8n8.x4.shared.b16 {%0,%1,%2,%3}, [%4];"
                    : "=r"(b0[0]), "=r"(b0[1]), "=r"(b1[0]), "=r"(b1[1])
                    : "r"(addr));
            }
#pragma unroll
            for (int mt = 0; mt < 2; ++mt)
#pragma unroll
                for (int nt = 0; nt < 2; ++nt) {
                    asm volatile(
                        "mma.sync.aligned.m16n8k16.row.col.f32.bf16.bf16.f32 "
                        "{%0,%1,%2,%3}, {%4,%5,%6,%7}, {%8,%9}, {%0,%1,%2,%3};"
                        : "+f"(c[mt][nt][0]), "+f"(c[mt][nt][1]),
                          "+f"(c[mt][nt][2]), "+f"(c[mt][nt][3])
                        : "r"(a0[mt]), "r"(a1[mt]), "r"(a2[mt]), "r"(a3[mt]),
                          "r"(b0[nt]), "r"(b1[nt]));
                }
        }
    }

    // ---- epilogue: register-local score, smem transpose, coalesced store ----
    __syncthreads();          // everyone past mainloop before smem reuse
    float* sc = (float*)smem; // 32 q x 64 i, stride LDS_SC
    const float Bv = g_B;
#pragma unroll
    for (int nt = 0; nt < 2; ++nt) {
        int q_local = wn * 8 + nt * 4 + (lane & 3);
        float c1v = g_c1[qBase + q_local];
#pragma unroll
        for (int mt = 0; mt < 2; ++mt) {
            int r0 = wm * 32 + mt * 16 + (lane >> 2);
            float num0 = c[mt][nt][0] + c1v;
            float den0 = c[mt][nt][1] + Bv;
            float num1 = c[mt][nt][2] + c1v;
            float den1 = c[mt][nt][3] + Bv;
            float s0 = num0 * rsqrtf(fmaxf(den0, 1e-24f));
            float s1 = num1 * rsqrtf(fmaxf(den1, 1e-24f));
            sc[q_local * LDS_SC + r0] = 1.f / (1.f + __expf(-s0));
            sc[q_local * LDS_SC + r0 + 8] = 1.f / (1.f + __expf(-s1));
        }
    }
    __syncthreads();

    {
        int q_local = tid >> 3;          // 0..31
        int i0 = (tid & 7) * 8;          // 0..56
        float* dst = out + (qBase + q_local) * NI + iBase + i0;
        const float* src = sc + q_local * LDS_SC + i0;
        *(float4*)(dst) = *(const float4*)(src);
        *(float4*)(dst + 4) = *(const float4*)(src + 4);
    }
}

extern "C" void kernel_launch(void* const* d_in, const int* in_sizes, int n_in,
                              void* d_out, int out_size) {
    const float* query_feats = (const float*)d_in[0];
    const float* query_img_feats = (const float*)d_in[1];
    const float* gallery_img_feats = (const float*)d_in[2];
    const float* bn_gamma = (const float*)d_in[3];
    const float* bn_beta = (const float*)d_in[4];
    const float* bn_mean = (const float*)d_in[5];
    const float* bn_var = (const float*)d_in[6];
    float* out = (float*)d_out;

    cudaFuncSetAttribute(score_mma, cudaFuncAttributeMaxDynamicSharedMemorySize,
                         SMEM_BYTES);

    prep<<<288, 256>>>(query_feats, query_img_feats, gallery_img_feats,
                       bn_gamma, bn_beta, bn_mean, bn_var);
    dim3 grid(NI / TM, (2 * NQ) / TN);
    score_mma<<<grid, 256, SMEM_BYTES>>>(out);
}

// round 14
// speedup vs baseline: 1.8387x; 1.8387x over previous
#include <cuda_runtime.h>
#include <cuda_bf16.h>
#include <cstdint>
#include <math.h>

#define NQ 256
#define ND 256
#define NI 2048
#define KTOT 512          // concat K: [yg | yg^2]
#define SE_INV_TEMP 5.0f
#define BN_EPS 1e-5f

// GEMM tile config
#define TM 64             // M tile (gallery i)
#define TN 64             // N tile (2 cols per query: num, den) -> 32 q per block
#define KC 128            // K per chunk (128 bf16 = 256 bytes per row)
#define NCHTOT (KTOT / KC)      // 4 chunks, single bf16 pass
#define LDAB 136          // smem row stride in bf16 (128 + 8 pad = 272 bytes)
#define A_STAGE_B (TM * LDAB * 2)            // 17408
#define B_STAGE_B (TN * LDAB * 2)            // 17408
#define STAGE_B (A_STAGE_B + B_STAGE_B)      // 34816
#define SMEM_BYTES (2 * STAGE_B)             // 69632 -> 2 CTAs/SM
#define LDS_SC 68         // float stride for score transpose (64 + 4)

// ---- device scratch (no allocs allowed) ----
__device__ __nv_bfloat16 g_Abf[NI * KTOT];     // [i][yg(256) | yg^2(256)]
__device__ __nv_bfloat16 g_Bbf[2 * NQ * KTOT]; // row 2q=[A1|0], 2q+1=[A3|A2]
__device__ float g_c1[NQ];
__device__ float g_B;

__device__ __forceinline__ uint32_t smem_to_u32(const void* p) {
    uint32_t a;
    asm("{ .reg .u64 t; cvta.to.shared.u64 t, %1; cvt.u32.u64 %0, t; }"
        : "=r"(a) : "l"(p));
    return a;
}
#define CP_ASYNC16(dst_u32, src_ptr) \
    asm volatile("cp.async.cg.shared.global [%0], [%1], 16;" \
                 :: "r"(dst_u32), "l"(src_ptr) : "memory")
#define CP_COMMIT() asm volatile("cp.async.commit_group;" ::: "memory")
#define CP_WAIT1() asm volatile("cp.async.wait_group 1;" ::: "memory")
#define CP_WAIT0() asm volatile("cp.async.wait_group 0;" ::: "memory")

__device__ __forceinline__ float warpSum(float v) {
#pragma unroll
    for (int o = 16; o > 0; o >>= 1) v += __shfl_xor_sync(0xffffffffu, v, o);
    return v;
}
__device__ __forceinline__ uint32_t pk2(float a, float b) {
    __nv_bfloat162 h = __floats2bfloat162_rn(a, b);
    return *reinterpret_cast<uint32_t*>(&h);
}
__device__ __forceinline__ void st8bf(__nv_bfloat16* p, const float* v) {
    uint4 u;
    u.x = pk2(v[0], v[1]); u.y = pk2(v[2], v[3]);
    u.z = pk2(v[4], v[5]); u.w = pk2(v[6], v[7]);
    *reinterpret_cast<uint4*>(p) = u;
}

// ---- fused prep: blocks [0,256) gallery rows, [256,288) query rows ----
__global__ __launch_bounds__(256) void prep(
    const float* __restrict__ qf, const float* __restrict__ qif,
    const float* __restrict__ gal,
    const float* __restrict__ gamma, const float* __restrict__ beta,
    const float* __restrict__ mean, const float* __restrict__ var) {
    int w = threadIdx.x >> 5, lane = threadIdx.x & 31;
    int d0 = lane * 8;

    if (blockIdx.x < 256) {
        int i = blockIdx.x * 8 + w;
        float v[8];
        *(float4*)&v[0] = *(const float4*)(gal + i * ND + d0);
        *(float4*)&v[4] = *(const float4*)(gal + i * ND + d0 + 4);
        float ss = 0.f;
#pragma unroll
        for (int j = 0; j < 8; ++j) ss += v[j] * v[j];
        ss = warpSum(ss);
        float r = 1.f / fmaxf(sqrtf(ss), 1e-12f);
        float yg[8], yg2[8];
#pragma unroll
        for (int j = 0; j < 8; ++j) { yg[j] = v[j] * r; yg2[j] = yg[j] * yg[j]; }
        st8bf(g_Abf + i * KTOT + d0, yg);
        st8bf(g_Abf + i * KTOT + ND + d0, yg2);
    } else {
        int q = (blockIdx.x - 256) * 8 + w;
        float gm[8], bt[8], mn[8], vr[8], x[8], y[8];
        *(float4*)&gm[0] = *(const float4*)(gamma + d0);
        *(float4*)&gm[4] = *(const float4*)(gamma + d0 + 4);
        *(float4*)&bt[0] = *(const float4*)(beta + d0);
        *(float4*)&bt[4] = *(const float4*)(beta + d0 + 4);
        *(float4*)&mn[0] = *(const float4*)(mean + d0);
        *(float4*)&mn[4] = *(const float4*)(mean + d0 + 4);
        *(float4*)&vr[0] = *(const float4*)(var + d0);
        *(float4*)&vr[4] = *(const float4*)(var + d0 + 4);
        *(float4*)&x[0] = *(const float4*)(qf + q * ND + d0);
        *(float4*)&x[4] = *(const float4*)(qf + q * ND + d0 + 4);
        *(float4*)&y[0] = *(const float4*)(qif + q * ND + d0);
        *(float4*)&y[4] = *(const float4*)(qif + q * ND + d0 + 4);

        float s[8], bb[8];
        float nx = 0.f, ny = 0.f;
#pragma unroll
        for (int j = 0; j < 8; ++j) {
            s[j] = gm[j] * rsqrtf(vr[j] + BN_EPS);
            bb[j] = bt[j] - mn[j] * s[j];
            nx += x[j] * x[j];
            ny += y[j] * y[j];
        }
        nx = warpSum(nx); ny = warpSum(ny);
        float rx = 1.f / fmaxf(sqrtf(nx), 1e-12f);
        float ry = 1.f / fmaxf(sqrtf(ny), 1e-12f);

        float ww[8], u[8];
        float nu = 0.f;
#pragma unroll
        for (int j = 0; j < 8; ++j) {
            float xh = x[j] * rx;
            float gate = 1.f / (1.f + __expf(-xh * SE_INV_TEMP));
            ww[j] = gate * s[j];
            u[j] = y[j] * ry * ww[j] + bb[j];
            nu += u[j] * u[j];
        }
        nu = warpSum(nu);
        float ru = 1.f / fmaxf(sqrtf(nu), 1e-12f);

        float a1[8], a2[8], a3[8], zz[8];
        float c1 = 0.f, Bacc = 0.f;
#pragma unroll
        for (int j = 0; j < 8; ++j) {
            float uh = u[j] * ru;
            a1[j] = uh * ww[j];
            a2[j] = ww[j] * ww[j];
            a3[j] = 2.f * ww[j] * bb[j];
            zz[j] = 0.f;
            c1 += uh * bb[j];
            Bacc += bb[j] * bb[j];
        }
        int r0 = (2 * q) * KTOT, r1 = (2 * q + 1) * KTOT;
        st8bf(g_Bbf + r0 + d0, a1);
        st8bf(g_Bbf + r0 + ND + d0, zz);
        st8bf(g_Bbf + r1 + d0, a3);
        st8bf(g_Bbf + r1 + ND + d0, a2);

        c1 = warpSum(c1);
        if (lane == 0) g_c1[q] = c1;
        if (q == 0) {
            Bacc = warpSum(Bacc);
            if (lane == 0) g_B = Bacc;
        }
    }
}

// ================= bf16 mma.sync GEMM + fused epilogue ======================
// out[q,i] = sigmoid((D[i,2q]+c1[q]) * rsqrt(D[i,2q+1]+B))
__global__ __launch_bounds__(256, 2) void score_mma(float* __restrict__ out) {
    extern __shared__ char smem[];
    const uint32_t smem_u = smem_to_u32(smem);
    const int tid = threadIdx.x;
    const int wid = tid >> 5, lane = tid & 31;
    const int wm = wid & 1;         // 0..1 -> 32-row band
    const int wn = wid >> 1;        // 0..3 -> 16-col band
    const int iBase = blockIdx.x * TM;
    const int nBase = blockIdx.y * TN;
    const int qBase = nBase >> 1;   // 32 q per block

    float c[2][2][4];
#pragma unroll
    for (int a = 0; a < 2; ++a)
#pragma unroll
        for (int b = 0; b < 2; ++b)
#pragma unroll
            for (int e = 0; e < 4; ++e) c[a][b][e] = 0.f;

    // per-thread ldmatrix base offsets (byte offsets within a stage)
    const int lmRow = lane & 15;
    const int lmColB = ((lane >> 4) & 1) * 16;
    uint32_t aOffs[2];
#pragma unroll
    for (int mt = 0; mt < 2; ++mt)
        aOffs[mt] = (uint32_t)((wm * 32 + mt * 16 + lmRow) * (LDAB * 2) + lmColB);
    const uint32_t bOff =
        (uint32_t)(A_STAGE_B + (wn * 16 + lmRow) * (LDAB * 2) + lmColB);

    // cp.async staging: A 64 rows x 16 x 16B = 1024 chunks (4/thread),
    //                   B 64 rows x 16 x 16B = 1024 chunks (4/thread)
    auto ISSUE = [&](int t, int buf) {
        uint32_t sA = smem_u + buf * STAGE_B;
        uint32_t sB = sA + A_STAGE_B;
#pragma unroll
        for (int j = 0; j < 4; ++j) {
            int cidx = tid + j * 256;            // [0, 1024)
            int row = cidx >> 4, c16 = cidx & 15;
            CP_ASYNC16(sA + row * (LDAB * 2) + c16 * 16,
                       g_Abf + (iBase + row) * KTOT + t * KC + c16 * 8);
        }
#pragma unroll
        for (int j = 0; j < 4; ++j) {
            int cidx = tid + j * 256;            // [0, 1024)
            int row = cidx >> 4, c16 = cidx & 15;
            CP_ASYNC16(sB + row * (LDAB * 2) + c16 * 16,
                       g_Bbf + (nBase + row) * KTOT + t * KC + c16 * 8);
        }
        CP_COMMIT();
    };

    ISSUE(0, 0);

#pragma unroll
    for (int u = 0; u < NCHTOT; ++u) {
        __syncthreads();   // stage (u+1)&1 reusable by the prefetch below
        if (u + 1 < NCHTOT) {
            ISSUE(u + 1, (u + 1) & 1);
            CP_WAIT1();    // group u complete (u+1 may still fly)
        } else {
            CP_WAIT0();
        }
        __syncthreads();   // chunk u data visible to all warps

        const uint32_t stage = smem_u + (u & 1) * STAGE_B;
#pragma unroll
        for (int kk = 0; kk < KC / 16; ++kk) {
            uint32_t a0[2], a1[2], a2[2], a3[2];
#pragma unroll
            for (int mt = 0; mt < 2; ++mt) {
                uint32_t addr = stage + aOffs[mt] + kk * 32;
                asm volatile(
                    "ldmatrix.sync.aligned.m8n8.x4.shared.b16 {%0,%1,%2,%3}, [%4];"
                    : "=r"(a0[mt]), "=r"(a1[mt]), "=r"(a2[mt]), "=r"(a3[mt])
                    : "r"(addr));
            }
            uint32_t b0[2], b1[2];
            {
                uint32_t addr = stage + bOff + kk * 32;
                asm volatile(
                    "ldmatrix.sync.aligned.m8n8.x4.shared.b16 {%0,%1,%2,%3}, [%4];"
                    : "=r"(b0[0]), "=r"(b0[1]), "=r"(b1[0]), "=r"(b1[1])
                    : "r"(addr));
            }
#pragma unroll
            for (int mt = 0; mt < 2; ++mt)
#pragma unroll
                for (int nt = 0; nt < 2; ++nt) {
                    asm volatile(
                        "mma.sync.aligned.m16n8k16.row.col.f32.bf16.bf16.f32 "
                        "{%0,%1,%2,%3}, {%4,%5,%6,%7}, {%8,%9}, {%0,%1,%2,%3};"
                        : "+f"(c[mt][nt][0]), "+f"(c[mt][nt][1]),
                          "+f"(c[mt][nt][2]), "+f"(c[mt][nt][3])
                        : "r"(a0[mt]), "r"(a1[mt]), "r"(a2[mt]), "r"(a3[mt]),
                          "r"(b0[nt]), "r"(b1[nt]));
                }
        }
    }

    // ---- epilogue: register-local score, smem transpose, coalesced store ----
    __syncthreads();          // everyone past mainloop before smem reuse
    float* sc = (float*)smem; // 32 q x 64 i, stride LDS_SC
    const float Bv = g_B;
#pragma unroll
    for (int nt = 0; nt < 2; ++nt) {
        int q_local = wn * 8 + nt * 4 + (lane & 3);
        float c1v = g_c1[qBase + q_local];
#pragma unroll
        for (int mt = 0; mt < 2; ++mt) {
            int r0 = wm * 32 + mt * 16 + (lane >> 2);
            float num0 = c[mt][nt][0] + c1v;
            float den0 = c[mt][nt][1] + Bv;
            float num1 = c[mt][nt][2] + c1v;
            float den1 = c[mt][nt][3] + Bv;
            float s0 = num0 * rsqrtf(fmaxf(den0, 1e-24f));
            float s1 = num1 * rsqrtf(fmaxf(den1, 1e-24f));
            sc[q_local * LDS_SC + r0] = 1.f / (1.f + __expf(-s0));
            sc[q_local * LDS_SC + r0 + 8] = 1.f / (1.f + __expf(-s1));
        }
    }
    __syncthreads();

    {
        int q_local = tid >> 3;          // 0..31
        int i0 = (tid & 7) * 8;          // 0..56
        float* dst = out + (qBase + q_local) * NI + iBase + i0;
        const float* src = sc + q_local * LDS_SC + i0;
        *(float4*)(dst) = *(const float4*)(src);
        *(float4*)(dst + 4) = *(const float4*)(src + 4);
    }
}

extern "C" void kernel_launch(void* const* d_in, const int* in_sizes, int n_in,
                              void* d_out, int out_size) {
    const float* query_feats = (const float*)d_in[0];
    const float* query_img_feats = (const float*)d_in[1];
    const float* gallery_img_feats = (const float*)d_in[2];
    const float* bn_gamma = (const float*)d_in[3];
    const float* bn_beta = (const float*)d_in[4];
    const float* bn_mean = (const float*)d_in[5];
    const float* bn_var = (const float*)d_in[6];
    float* out = (float*)d_out;

    cudaFuncSetAttribute(score_mma, cudaFuncAttributeMaxDynamicSharedMemorySize,
                         SMEM_BYTES);

    prep<<<288, 256>>>(query_feats, query_img_feats, gallery_img_feats,
                       bn_gamma, bn_beta, bn_mean, bn_var);
    dim3 grid(NI / TM, (2 * NQ) / TN);
    score_mma<<<grid, 256, SMEM_BYTES>>>(out);
}